// round 17
// baseline (speedup 1.0000x reference)
#include <cuda_runtime.h>
#include <cuda_fp16.h>
#include <cstdint>

// ---------------------------------------------------------------------------
// WindowAttention (Swin-style), GB300 sm_103a — fused kernel, R17.
// Base = R16 (f16/m16n8k16 datapath, head-decoupled). Change: rel-pos bias
// and ul/lr masks precomputed into FRAGMENT-ORDERED fp32 tables
// g_biasF/g_ulF/g_lrF[s][lane][32] — phase C reads them with coalesced
// L1-resident LDG.128 instead of conflicted smem/global gathers + index ALU.
// ---------------------------------------------------------------------------

__device__ uint32_t g_wqkvF[48 * 8 * 64];   // head-major [n8'][step16][lane][2]
__device__ uint32_t g_woutF[16 * 8 * 64];
__device__ float    g_biasF[4 * 32 * 32];   // [s][lane][rh*16 + nt*2 + u]
__device__ float    g_ulF[4 * 32 * 32];
__device__ float    g_lrF[4 * 32 * 32];

__device__ __forceinline__ uint32_t f2h2(float lo, float hi) {
    uint32_t r;
    asm("cvt.rn.f16x2.f32 %0, %1, %2;" : "=r"(r) : "f"(hi), "f"(lo));
    return r;
}

__device__ __forceinline__ void mma16(float* c, const uint32_t* a, const uint32_t* b) {
    asm volatile(
        "mma.sync.aligned.m16n8k16.row.col.f32.f16.f16.f32 "
        "{%0,%1,%2,%3}, {%4,%5,%6,%7}, {%8,%9}, {%0,%1,%2,%3};\n"
        : "+f"(c[0]), "+f"(c[1]), "+f"(c[2]), "+f"(c[3])
        : "r"(a[0]), "r"(a[1]), "r"(a[2]), "r"(a[3]), "r"(b[0]), "r"(b[1]));
}

// ===========================================================================
// cvt: weights -> f16 fragment-linear; bias/masks -> fragment-ordered fp32.
// ===========================================================================
__global__ void cvt_kernel(const float* __restrict__ wqkv,
                           const float* __restrict__ wout,
                           const float* __restrict__ pe,
                           const float* __restrict__ ul,
                           const float* __restrict__ lr) {
    int w = blockIdx.x * 256 + threadIdx.x;   // 0..24575
    {
        int hw = w & 1, lane = (w >> 1) & 31, step = (w >> 6) & 7, n8p = w >> 9;
        int h = n8p / 12, p = n8p % 12;
        int n = (p >> 2) * 128 + h * 32 + (p & 3) * 8 + (lane >> 2);
        int k = step * 16 + 2 * (lane & 3) + hw * 8;
        g_wqkvF[w] = f2h2(wqkv[k * 384 + n], wqkv[(k + 1) * 384 + n]);
    }
    if (w < 16 * 8 * 64) {
        int hw = w & 1, lane = (w >> 1) & 31, step = (w >> 6) & 7, n8 = w >> 9;
        int n = n8 * 8 + (lane >> 2);
        int k = step * 16 + 2 * (lane & 3) + hw * 8;
        g_woutF[w] = f2h2(wout[k * 128 + n], wout[(k + 1) * 128 + n]);
    }
    if (w < 4096) {
        int s = w >> 10, lane = (w >> 5) & 31, slot = w & 31;
        int rh = slot >> 4, r = slot & 15;
        int nt = r >> 1, u = r & 1;
        int gid = lane >> 2, tid4 = lane & 3;
        int i = s * 16 + rh * 8 + gid;
        int j = nt * 8 + tid4 * 2 + u;
        int iy = i >> 3, ix = i & 7, jy = j >> 3, jx = j & 7;
        g_biasF[w] = pe[(jy - iy + 7) * 15 + (jx - ix + 7)];
        g_ulF[w]   = ul[i * 64 + j];
        g_lrF[w]   = lr[i * 64 + j];
    }
}

// ===========================================================================
// smem map (u32):
//  sQ  0..4608      [64 tok][144h]  (stride 72 u32)
//  sK  4608..9216   [64 tok][144h]
//  sVT 9216..14336  [128 d][80h]    transposed V (stride 40 u32)
//  sA  14336..18944 [64 row][144h]  (P1 A)
//  sO  18944..23552 [64 tok][144h]  (written in F, read in G)
//  sP  23552..33792 4 heads x [64 tok][80h]
//  BO  33792..33920    total 33920 u32 = 135680 B
// ===========================================================================
#define SQ_OFF  0
#define SK_OFF  4608
#define SVT_OFF 9216
#define SA_OFF  14336
#define SO_OFF  18944
#define SP_OFF  23552
#define BO_OFF  33792
#define FU_SMEM (33920 * 4)

__global__ __launch_bounds__(512, 1)
void fused_kernel(const float* __restrict__ x,
                  const float* __restrict__ bout,
                  float* __restrict__ out) {
    extern __shared__ uint32_t sm[];
    uint32_t* sQ  = sm + SQ_OFF;
    uint32_t* sK  = sm + SK_OFF;
    uint32_t* sVT = sm + SVT_OFF;
    uint32_t* sA  = sm + SA_OFF;
    uint32_t* sO  = sm + SO_OFF;
    uint32_t* sP  = sm + SP_OFF;
    float* sBO = (float*)(sm + BO_OFF);

    const int t = threadIdx.x;
    const int warp = t >> 5, lane = t & 31;
    const int gid = lane >> 2, tid4 = lane & 3;
    const int blk = blockIdx.x;
    const int bb = blk >> 8, win = blk & 255;
    const int wy = win >> 4, wx = win & 15;

    // warp role: head h, sub-slice s (24 of the 96 head cols)
    const int head = warp >> 2, s = warp & 3;
    const int hoff = head * 32;
    const int wrb = s * 16;                  // attention q-row base

    // B fragment loader: 3 n8'-tiles, one LDG.64 (b0,b1) each
    uint2 bA[3], bB[3];
    auto ldBkt = [&](uint2* dst, int step) {
        #pragma unroll
        for (int nt = 0; nt < 3; nt++) {
            int n8p = head * 12 + s * 3 + nt;
            dst[nt] = *(const uint2*)&g_wqkvF[((n8p * 8 + step) * 32 + lane) * 2];
        }
    };
    ldBkt(bA, 0);
    ldBkt(bB, 1);

    // ---- A gather: rolled x rows -> f16 16-slot-interleaved rows ----
    {
        const int row_a = t >> 3, part = t & 7;
        const int ty = row_a >> 3, tx = row_a & 7;
        const int sh = (wy * 8 + ty + 4) & 127, sw = (wx * 8 + tx + 4) & 127;
        const float* aptr = x + (((size_t)bb * 128 + sh) * 128 + sw) * 128 + part * 16;
        float v[16];
        #pragma unroll
        for (int j4 = 0; j4 < 4; j4++) {
            float4 q4 = *(const float4*)(aptr + j4 * 4);
            v[j4 * 4 + 0] = q4.x; v[j4 * 4 + 1] = q4.y;
            v[j4 * 4 + 2] = q4.z; v[j4 * 4 + 3] = q4.w;
        }
        uint32_t* ap = sA + row_a * 72 + part * 8;
        uint4 w0, w1;
        w0.x = f2h2(v[0],  v[1]);  w0.y = f2h2(v[8],  v[9]);
        w0.z = f2h2(v[2],  v[3]);  w0.w = f2h2(v[10], v[11]);
        w1.x = f2h2(v[4],  v[5]);  w1.y = f2h2(v[12], v[13]);
        w1.z = f2h2(v[6],  v[7]);  w1.w = f2h2(v[14], v[15]);
        *(uint4*)&ap[0] = w0;
        *(uint4*)&ap[4] = w1;
    }
    if (t < 128) sBO[t] = bout[t];
    __syncthreads();                         // [FULL SYNC 1]

    // ---- Phase 1: QKV slice GEMM, 64 rows x 24 cols per warp, 8 k16-steps ----
    float acc[4][3][4];
    #pragma unroll
    for (int a = 0; a < 4; a++)
        #pragma unroll
        for (int b2 = 0; b2 < 3; b2++)
            #pragma unroll
            for (int c = 0; c < 4; c++) acc[a][b2][c] = 0.f;

    {
        const uint32_t* aR = &sA[gid * 72 + 2 * tid4];
        #pragma unroll
        for (int step = 0; step < 8; step++) {
            const uint2* bf = (step & 1) ? bB : bA;
            uint2 ar[8];
            #pragma unroll
            for (int r = 0; r < 8; r++)
                ar[r] = *(const uint2*)(aR + r * (8 * 72) + step * 8);
            #pragma unroll
            for (int mt = 0; mt < 4; mt++) {
                uint32_t am[4] = {ar[2 * mt].x, ar[2 * mt + 1].x,
                                  ar[2 * mt].y, ar[2 * mt + 1].y};
                #pragma unroll
                for (int nt = 0; nt < 3; nt++)
                    mma16(acc[mt][nt], am, (const uint32_t*)&bf[nt]);
            }
            if (step + 2 < 8) ldBkt((step & 1) ? bB : bA, step + 2);
        }
    }

    // epilogue: Q,K -> row-major 16-slot rows; V -> transposed sVT
    {
        #pragma unroll
        for (int mt = 0; mt < 4; mt++) {
            int r0 = mt * 16 + gid, r1 = r0 + 8;
            #pragma unroll
            for (int nt = 0; nt < 3; nt++) {
                int p = s * 3 + nt;
                int seg = p >> 2;
                if (seg < 2) {
                    uint32_t* dst = (seg == 0 ? sQ : sK);
                    int off = (2 * head + ((p & 3) >> 1)) * 8 + 2 * tid4 + (p & 1);
                    dst[r0 * 72 + off] = f2h2(acc[mt][nt][0], acc[mt][nt][1]);
                    dst[r1 * 72 + off] = f2h2(acc[mt][nt][2], acc[mt][nt][3]);
                } else {
                    int d = hoff + (p & 3) * 8 + 2 * tid4;
                    int posg = 4 * (gid >> 1) + (gid & 1);
                    __half* vh = (__half*)sVT;
                    vh[d * 80 + mt * 16 + posg]           = __float2half_rn(acc[mt][nt][0]);
                    vh[(d + 1) * 80 + mt * 16 + posg]     = __float2half_rn(acc[mt][nt][1]);
                    vh[d * 80 + mt * 16 + posg + 2]       = __float2half_rn(acc[mt][nt][2]);
                    vh[(d + 1) * 80 + mt * 16 + posg + 2] = __float2half_rn(acc[mt][nt][3]);
                }
            }
        }
    }
    // per-head barrier: head h's Q/K/V slice complete
    asm volatile("bar.sync %0, %1;" :: "r"(1 + head), "r"(128) : "memory");

    // ---- Phase B: S = Q K^T (2 k16-steps) ----
    float sacc[8][4];
    #pragma unroll
    for (int b2 = 0; b2 < 8; b2++)
        #pragma unroll
        for (int c = 0; c < 4; c++) sacc[b2][c] = 0.f;

    #pragma unroll
    for (int st = 0; st < 2; st++) {
        int off = (2 * head + st) * 8 + 2 * tid4;
        uint2 a0 = *(const uint2*)&sQ[(wrb + gid) * 72 + off];
        uint2 a1 = *(const uint2*)&sQ[(wrb + 8 + gid) * 72 + off];
        uint32_t a[4] = {a0.x, a1.x, a0.y, a1.y};
        #pragma unroll
        for (int nt = 0; nt < 8; nt++) {
            uint2 b = *(const uint2*)&sK[(nt * 8 + gid) * 72 + off];
            mma16(sacc[nt], a, (const uint32_t*)&b);
        }
    }

    // ---- Phase C: bias (+masks) + softmax, fragment-ordered tables ----
    const float scale = 0.17677669529663689f;
    const bool addUL = (wy == 15);
    const bool addLR = (wx == 15);
    const int tbase = (s * 32 + lane) * 32;

    #pragma unroll
    for (int rh = 0; rh < 2; rh++) {
        float bf[16], uf[16], lf[16];
        #pragma unroll
        for (int q = 0; q < 4; q++)
            *(float4*)&bf[q * 4] = *(const float4*)&g_biasF[tbase + rh * 16 + q * 4];
        if (addUL) {
            #pragma unroll
            for (int q = 0; q < 4; q++)
                *(float4*)&uf[q * 4] = *(const float4*)&g_ulF[tbase + rh * 16 + q * 4];
        }
        if (addLR) {
            #pragma unroll
            for (int q = 0; q < 4; q++)
                *(float4*)&lf[q * 4] = *(const float4*)&g_lrF[tbase + rh * 16 + q * 4];
        }
        float vrow[16];
        float m = -1e30f;
        #pragma unroll
        for (int e = 0; e < 16; e++) {
            float v = sacc[e >> 1][rh * 2 + (e & 1)] * scale + bf[e];
            if (addUL) v += uf[e];
            if (addLR) v += lf[e];
            vrow[e] = v;
            m = fmaxf(m, v);
        }
        m = fmaxf(m, __shfl_xor_sync(0xffffffffu, m, 1));
        m = fmaxf(m, __shfl_xor_sync(0xffffffffu, m, 2));
        float sum = 0.f;
        #pragma unroll
        for (int e = 0; e < 16; e++) {
            vrow[e] = __expf(vrow[e] - m);
            sum += vrow[e];
        }
        sum += __shfl_xor_sync(0xffffffffu, sum, 1);
        sum += __shfl_xor_sync(0xffffffffu, sum, 2);
        float inv = 1.f / sum;
        #pragma unroll
        for (int e = 0; e < 16; e++)
            sacc[e >> 1][rh * 2 + (e & 1)] = vrow[e] * inv;
    }

    // ---- Phase D: store P (f16, 16-slot rows, stride 40 u32) ----
    uint32_t* myP = sP + head * (64 * 40);
    #pragma unroll
    for (int rh = 0; rh < 2; rh++) {
        int row = wrb + rh * 8 + gid;
        #pragma unroll
        for (int nt = 0; nt < 8; nt++) {
            myP[row * 40 + (nt >> 1) * 8 + 2 * tid4 + (nt & 1)] =
                f2h2(sacc[nt][rh * 2], sacc[nt][rh * 2 + 1]);
        }
    }
    // per-head barrier: sP[head] coherent
    asm volatile("bar.sync %0, %1;" :: "r"(1 + head), "r"(128) : "memory");

    // ---- Phase E: O = P @ V (4 k16-steps over 64 keys) ----
    float oacc[4][4];
    #pragma unroll
    for (int b2 = 0; b2 < 4; b2++)
        #pragma unroll
        for (int c = 0; c < 4; c++) oacc[b2][c] = 0.f;

    #pragma unroll
    for (int st = 0; st < 4; st++) {
        uint2 a0 = *(const uint2*)&myP[(wrb + gid) * 40 + st * 8 + 2 * tid4];
        uint2 a1 = *(const uint2*)&myP[(wrb + 8 + gid) * 40 + st * 8 + 2 * tid4];
        uint32_t a[4] = {a0.x, a1.x, a0.y, a1.y};
        #pragma unroll
        for (int nt = 0; nt < 4; nt++) {
            uint2 b = *(const uint2*)&sVT[(hoff + nt * 8 + gid) * 40 + st * 8 + 2 * tid4];
            mma16(oacc[nt], a, (const uint32_t*)&b);
        }
    }

    // ---- Phase F: store O into sO (row-major 16-slot, stride 72 u32) ----
    #pragma unroll
    for (int nt = 0; nt < 4; nt++) {
        int off = (2 * head + (nt >> 1)) * 8 + 2 * tid4 + (nt & 1);
        sO[(wrb + gid) * 72 + off]     = f2h2(oacc[nt][0], oacc[nt][1]);
        sO[(wrb + 8 + gid) * 72 + off] = f2h2(oacc[nt][2], oacc[nt][3]);
    }
    __syncthreads();                         // [FULL SYNC 2] all heads' O ready

    // ---- Phase G: Y = O @ w_out + b_out (8 k16-steps) ----
    const int pwm = warp & 3, pwn = warp >> 2;   // 4x4 grid, tile 16x32
    float yacc[4][4];
    #pragma unroll
    for (int b2 = 0; b2 < 4; b2++)
        #pragma unroll
        for (int c = 0; c < 4; c++) yacc[b2][c] = 0.f;

    uint2 wA[4], wB[4];
    auto ldW = [&](uint2* dst, int step) {
        #pragma unroll
        for (int nt = 0; nt < 4; nt++) {
            int n8g = pwn * 4 + nt;
            dst[nt] = *(const uint2*)&g_woutF[((n8g * 8 + step) * 32 + lane) * 2];
        }
    };
    ldW(wA, 0);
    ldW(wB, 1);

    const uint32_t* oR0 = &sO[(pwm * 16 + gid) * 72 + 2 * tid4];
    const uint32_t* oR1 = oR0 + 8 * 72;
    #pragma unroll
    for (int step = 0; step < 8; step++) {
        uint2 a0 = *(const uint2*)(oR0 + step * 8);
        uint2 a1 = *(const uint2*)(oR1 + step * 8);
        uint32_t a[4] = {a0.x, a1.x, a0.y, a1.y};
        const uint2* wf = (step & 1) ? wB : wA;
        #pragma unroll
        for (int nt = 0; nt < 4; nt++)
            mma16(yacc[nt], a, (const uint32_t*)&wf[nt]);
        if (step + 2 < 8) ldW((step & 1) ? wB : wA, step + 2);
    }

    #pragma unroll
    for (int rh = 0; rh < 2; rh++) {
        int i = pwm * 16 + rh * 8 + gid;
        int ty = i >> 3, tx = i & 7;
        int h = (wy * 8 + ty + 4) & 127;
        int w = (wx * 8 + tx + 4) & 127;
        float* orow = out + (((size_t)bb * 128 + h) * 128 + w) * 128;
        #pragma unroll
        for (int nt = 0; nt < 4; nt++) {
            int c = pwn * 32 + nt * 8 + tid4 * 2;
            float2 v = make_float2(yacc[nt][rh * 2]     + sBO[c],
                                   yacc[nt][rh * 2 + 1] + sBO[c + 1]);
            *(float2*)(orow + c) = v;
        }
    }
}

// ===========================================================================
extern "C" void kernel_launch(void* const* d_in, const int* in_sizes, int n_in,
                              void* d_out, int out_size) {
    const float* x    = (const float*)d_in[0];
    const float* wqkv = (const float*)d_in[1];
    const float* wout = (const float*)d_in[2];
    const float* bout = (const float*)d_in[3];
    const float* pe   = (const float*)d_in[4];
    const float* ul   = (const float*)d_in[5];
    const float* lr   = (const float*)d_in[6];
    float* out = (float*)d_out;

    cudaFuncSetAttribute(fused_kernel, cudaFuncAttributeMaxDynamicSharedMemorySize, FU_SMEM);

    cvt_kernel<<<96, 256>>>(wqkv, wout, pe, ul, lr);
    fused_kernel<<<4096, 512, FU_SMEM>>>(x, bout, out);
}